// round 10
// baseline (speedup 1.0000x reference)
#include <cuda_runtime.h>
#include <cuda_bf16.h>

// Problem constants
#define B    32
#define LQ   32
#define DLEN 4096
#define P    16
#define D    2048
#define H    2048
#define V    50257
#define VPAD 50432            // 394 * 128

#define KSPLIT 32             // k-split for skinny GEMMs
#define TILE_N 64
#define KB     64
#define KCH    8              // k-chunks in ydot (256 d's each)
#define YROWS  128            // compact rows per ydot block

// ---------------- scratch (device globals; no allocation allowed) ----------------
__device__ float g_qrep[B * D];
__device__ float g_qenc[B * H];
__device__ float g_v[B * D];
__device__ float g_part[KSPLIT * B * 2048];      // GEMM partials (8 MB)
__device__ float g_c[B];
__device__ unsigned int g_mask[VPAD];            // per-id batch mask; self-cleaned
__device__ int   g_ids[VPAD];
__device__ unsigned int g_cmask[VPAD];
__device__ int   g_rank[V];
__device__ int   g_nids;
__device__ int   g_cntA[2048 / TILE_N];          // gemmA fixup counters (self-reset)
__device__ int   g_cntB[2048 / TILE_N];          // gemmB fixup counters (self-reset)
__device__ float g_yp[(size_t)VPAD * 256];       // chunk partials [slot][z*32+b]

// ---------------- mark: batch mask per used vocab id (also zeroes g_nids) ----------
__global__ void k_mark(const int* __restrict__ docs,
                       const int* __restrict__ plen) {
    int b = blockIdx.x;
    __shared__ int tot;
    if (threadIdx.x == 0) {
        int s = 0;
        #pragma unroll
        for (int q = 0; q < P; q++) s += plen[b * P + q];
        tot = s;
        if (b == 0) g_nids = 0;   // no reader until k_compact (next kernel)
    }
    __syncthreads();
    unsigned bit = 1u << b;
    for (int tt = threadIdx.x; tt < tot; tt += blockDim.x)
        atomicOr(&g_mask[docs[b * DLEN + tt]], bit);
}

// ---------------- compact used ids + masks; block-aggregated atomics ---------------
__global__ void k_compact() {
    __shared__ int warp_off[8];
    __shared__ int block_base;
    int i = blockIdx.x * 256 + threadIdx.x;
    unsigned m = (i < V) ? g_mask[i] : 0u;
    bool has = (m != 0u);
    if (has) g_mask[i] = 0u;                     // self-clean for next call
    unsigned ballot = __ballot_sync(0xFFFFFFFFu, has);
    int w = threadIdx.x >> 5, lane = threadIdx.x & 31;
    if (lane == 0) warp_off[w] = __popc(ballot);
    __syncthreads();
    if (threadIdx.x == 0) {
        int tot = 0;
        #pragma unroll
        for (int j = 0; j < 8; j++) { int c = warp_off[j]; warp_off[j] = tot; tot += c; }
        block_base = tot ? atomicAdd(&g_nids, tot) : 0;
    }
    __syncthreads();
    if (has) {
        int slot = block_base + warp_off[w] + __popc(ballot & ((1u << lane) - 1u));
        g_ids[slot] = i;
        g_cmask[slot] = m;
        g_rank[i] = slot;
    }
}

// ---------------- q_rep = masked mean of query token embeddings ----------------
__global__ void k_qrep(const int* __restrict__ queries,
                       const int* __restrict__ qlen,
                       const float* __restrict__ emb) {
    int b = blockIdx.x;
    __shared__ int toks[LQ];
    if (threadIdx.x < LQ) toks[threadIdx.x] = queries[b * LQ + threadIdx.x];
    int len = qlen[b];
    __syncthreads();
    float inv = 1.0f / (float)len;
    int d = blockIdx.y * 256 + threadIdx.x;
    float s = 0.0f;
    for (int l = 0; l < len; l++) s += emb[(size_t)toks[l] * D + d];
    g_qrep[b * D + d] = s * inv;
}

// ---------------- fused skinny GEMM + deterministic last-block reduce ---------------
// C[32,2048] = A[32,2048] x W^(T) (+bias). grid (32, KSPLIT). The last k-split
// block per n-tile sums all 32 partials IN FIXED ORDER (deterministic) into C.
__global__ void k_gemm(const float* __restrict__ A,
                       const float* __restrict__ W,
                       int transW,
                       float* __restrict__ C,
                       const float* __restrict__ bias,
                       int addBias,
                       int* __restrict__ cnt) {
    const int n0 = blockIdx.x * TILE_N;
    const int k0 = blockIdx.y * KB;
    __shared__ float As[32][KB];
    __shared__ float Ws[TILE_N][KB + 1];
    __shared__ int isTail;

    const int t  = threadIdx.x;      // 256 threads
    const int tb = t >> 5;
    const int tn = t & 31;

    #pragma unroll
    for (int i = 0; i < 8; i++) {
        int flat = t + i * 256;
        int bb = flat >> 6, kk = flat & 63;
        As[bb][kk] = A[bb * 2048 + k0 + kk];
    }
    if (!transW) {
        #pragma unroll
        for (int i = 0; i < 16; i++) {
            int flat = t + i * 256;
            int nn = flat >> 6, kk = flat & 63;
            Ws[nn][kk] = W[(size_t)(n0 + nn) * 2048 + k0 + kk];
        }
    } else {
        #pragma unroll
        for (int i = 0; i < 16; i++) {
            int flat = t + i * 256;
            int nn = flat & 63, kk = flat >> 6;
            Ws[nn][kk] = W[(size_t)(k0 + kk) * 2048 + n0 + nn];
        }
    }
    __syncthreads();

    float acc00 = 0.f, acc01 = 0.f, acc10 = 0.f, acc11 = 0.f;
    float acc20 = 0.f, acc21 = 0.f, acc30 = 0.f, acc31 = 0.f;
    #pragma unroll 16
    for (int k = 0; k < KB; k++) {
        float a0 = As[tb * 4 + 0][k];
        float a1 = As[tb * 4 + 1][k];
        float a2 = As[tb * 4 + 2][k];
        float a3 = As[tb * 4 + 3][k];
        float w0 = Ws[tn][k];
        float w1 = Ws[tn + 32][k];
        acc00 += a0 * w0; acc01 += a0 * w1;
        acc10 += a1 * w0; acc11 += a1 * w1;
        acc20 += a2 * w0; acc21 += a2 * w1;
        acc30 += a3 * w0; acc31 += a3 * w1;
    }

    float* out = g_part + (size_t)blockIdx.y * 32 * 2048;
    out[(tb * 4 + 0) * 2048 + n0 + tn]      = acc00;
    out[(tb * 4 + 0) * 2048 + n0 + tn + 32] = acc01;
    out[(tb * 4 + 1) * 2048 + n0 + tn]      = acc10;
    out[(tb * 4 + 1) * 2048 + n0 + tn + 32] = acc11;
    out[(tb * 4 + 2) * 2048 + n0 + tn]      = acc20;
    out[(tb * 4 + 2) * 2048 + n0 + tn + 32] = acc21;
    out[(tb * 4 + 3) * 2048 + n0 + tn]      = acc30;
    out[(tb * 4 + 3) * 2048 + n0 + tn + 32] = acc31;

    // --- deterministic fixup: last-arriving block for this n-tile reduces ---
    __threadfence();
    __syncthreads();
    if (t == 0) isTail = (atomicAdd(&cnt[blockIdx.x], 1) == KSPLIT - 1) ? 1 : 0;
    __syncthreads();
    if (!isTail) return;

    // thread t: row = t>>3, 8 consecutive cols at (t&7)*8 (two float4)
    const int row = t >> 3;
    const int c8  = (t & 7) * 8;
    float4 s0 = make_float4(0.f, 0.f, 0.f, 0.f);
    float4 s1 = make_float4(0.f, 0.f, 0.f, 0.f);
    #pragma unroll
    for (int sp = 0; sp < KSPLIT; sp++) {
        const float4* p = (const float4*)(g_part + (size_t)sp * 65536 + row * 2048 + n0 + c8);
        float4 x = __ldcg(p);
        float4 y = __ldcg(p + 1);
        s0.x += x.x; s0.y += x.y; s0.z += x.z; s0.w += x.w;
        s1.x += y.x; s1.y += y.y; s1.z += y.z; s1.w += y.w;
    }
    if (addBias) {
        const float4* bp = (const float4*)(bias + n0 + c8);
        float4 b0 = bp[0], b1 = bp[1];
        s0.x += b0.x; s0.y += b0.y; s0.z += b0.z; s0.w += b0.w;
        s1.x += b1.x; s1.y += b1.y; s1.z += b1.z; s1.w += b1.w;
    }
    float4* cp = (float4*)(C + row * 2048 + n0 + c8);
    cp[0] = s0;
    cp[1] = s1;
    if (t == 0) cnt[blockIdx.x] = 0;     // self-reset for next replay
}

// c[b] = q_enc[b] . bias
__global__ void k_qc(const float* __restrict__ bias) {
    int b = blockIdx.x;
    float s = 0.0f;
    for (int i = threadIdx.x; i < H; i += 256) s += g_qenc[b * H + i] * bias[i];
    __shared__ float red[256];
    red[threadIdx.x] = s;
    __syncthreads();
    for (int o = 128; o; o >>= 1) {
        if (threadIdx.x < o) red[threadIdx.x] += red[threadIdx.x + o];
        __syncthreads();
    }
    if (threadIdx.x == 0) g_c[b] = red[0];
}

// ---------------- ydot: per compact row, dot against ONLY the batches in its mask ----
// grid (VPAD/YROWS, KCH). 256 threads; block stages v k-chunk (32 KB) once;
// one warp per 16 rows; sector-perfect lane loads; dual-batch shfl interleave.
__global__ __launch_bounds__(256, 5) void k_ydot(const float* __restrict__ emb) {
    const int z  = blockIdx.y;
    const int m0 = blockIdx.x * YROWS;
    const int nids = g_nids;
    if (m0 >= nids) return;

    __shared__ float4 vs[32][64];    // v chunk [b][j], 32 KB
    __shared__ int ids_s[YROWS];
    __shared__ unsigned mask_s[YROWS];

    const int t = threadIdx.x, w = t >> 5, lane = t & 31;

    #pragma unroll
    for (int i = 0; i < 8; i++) {
        int idx = t + i * 256;               // 0..2047 float4s
        int b = idx >> 6, j = idx & 63;
        vs[b][j] = *(const float4*)(g_v + (size_t)b * D + z * 256 + j * 4);
    }
    if (t < YROWS) {
        int gi = m0 + t;
        bool val = gi < nids;
        ids_s[t]  = val ? g_ids[gi] : 0;
        mask_s[t] = val ? g_cmask[gi] : 0u;
    }
    __syncthreads();

    const int rbase = w * 16;                // warp w handles 16 rows
    const size_t zbase = (size_t)z * 256;

    // depth-2 row pipeline; lane loads CONTIGUOUS float4s (full-sector LDG.128)
    float4 ba0, bb0, ba1, bb1;
    {
        const float4* rp = (const float4*)(emb + (size_t)ids_s[rbase] * D + zbase);
        ba0 = rp[lane]; bb0 = rp[lane + 32];
    }
    {
        const float4* rp = (const float4*)(emb + (size_t)ids_s[rbase + 1] * D + zbase);
        ba1 = rp[lane]; bb1 = rp[lane + 32];
    }

    #pragma unroll 1
    for (int r = 0; r < 16; r++) {
        float4 ea, eb;
        if (r & 1) { ea = ba1; eb = bb1; } else { ea = ba0; eb = bb0; }
        if (r + 2 < 16) {
            const float4* rp = (const float4*)(emb + (size_t)ids_s[rbase + r + 2] * D + zbase);
            if (r & 1) { ba1 = rp[lane]; bb1 = rp[lane + 32]; }
            else       { ba0 = rp[lane]; bb0 = rp[lane + 32]; }
        }
        unsigned mask = mask_s[rbase + r];
        const int slot = m0 + rbase + r;
        while (mask) {
            int b0 = __ffs(mask) - 1; mask &= mask - 1;
            int b1 = -1;
            if (mask) { b1 = __ffs(mask) - 1; mask &= mask - 1; }
            float4 v0a = vs[b0][lane], v0b = vs[b0][lane + 32];
            float s0 = ea.x * v0a.x + ea.y * v0a.y + ea.z * v0a.z + ea.w * v0a.w
                     + eb.x * v0b.x + eb.y * v0b.y + eb.z * v0b.z + eb.w * v0b.w;
            float s1 = 0.0f;
            if (b1 >= 0) {
                float4 v1a = vs[b1][lane], v1b = vs[b1][lane + 32];
                s1 = ea.x * v1a.x + ea.y * v1a.y + ea.z * v1a.z + ea.w * v1a.w
                   + eb.x * v1b.x + eb.y * v1b.y + eb.z * v1b.z + eb.w * v1b.w;
            }
            // two independent shfl chains, interleaved -> latency overlapped
            #pragma unroll
            for (int o = 16; o; o >>= 1) {
                s0 += __shfl_xor_sync(0xFFFFFFFFu, s0, o);
                s1 += __shfl_xor_sync(0xFFFFFFFFu, s1, o);
            }
            if (lane == 0) {
                g_yp[(size_t)slot * 256 + z * 32 + b0] = s0;
                if (b1 >= 0) g_yp[(size_t)slot * 256 + z * 32 + b1] = s1;
            }
        }
    }
}

// ---------------- scatter: score[b,p] = mean_token sum_z yp[rank[tok]][z][b] + c[b] --
__global__ void k_scatter(const int* __restrict__ docs,
                          const int* __restrict__ plen,
                          float* __restrict__ out) {
    const int bp = blockIdx.x;           // 512 blocks
    const int b = bp >> 4, p = bp & 15;
    const int t = threadIdx.x;           // 128 threads
    __shared__ int info[2];
    __shared__ float red[128];

    if (t == 0) {
        int start = 0;
        for (int q = 0; q < p; q++) start += plen[b * P + q];
        info[0] = start;
        info[1] = plen[b * P + p];
    }
    __syncthreads();
    const int start = info[0], len = info[1];

    float s = 0.0f;
    for (int tt = t; tt < len; tt += 128) {
        int tok = docs[b * DLEN + start + tt];
        const float* yb = g_yp + (size_t)g_rank[tok] * 256 + b;
        // fixed summation order over the 8 k-chunks -> deterministic
        float s01 = yb[0 * 32] + yb[1 * 32];
        float s23 = yb[2 * 32] + yb[3 * 32];
        float s45 = yb[4 * 32] + yb[5 * 32];
        float s67 = yb[6 * 32] + yb[7 * 32];
        s += (s01 + s23) + (s45 + s67);
    }
    red[t] = s;
    __syncthreads();
    for (int o = 64; o; o >>= 1) {
        if (t < o) red[t] += red[t + o];
        __syncthreads();
    }
    if (t == 0) {
        float denom = (float)(len > 0 ? len : 1);
        out[bp] = (len > 0) ? (red[0] / denom + g_c[b]) : 0.0f;
    }
}

// ---------------- launch: ydot is the 6th submitted kernel (ncu -s 5 captures it) ----
extern "C" void kernel_launch(void* const* d_in, const int* in_sizes, int n_in,
                              void* d_out, int out_size) {
    const int*   queries = (const int*)d_in[0];
    const int*   qlen    = (const int*)d_in[1];
    const int*   docs    = (const int*)d_in[2];
    const int*   plen    = (const int*)d_in[3];
    const float* emb     = (const float*)d_in[4];
    const float* W       = (const float*)d_in[5];
    const float* bias    = (const float*)d_in[6];
    float*       out     = (float*)d_out;

    float *qrep_p, *qenc_p, *v_p;
    int *cntA_p, *cntB_p;
    cudaGetSymbolAddress((void**)&qrep_p, g_qrep);
    cudaGetSymbolAddress((void**)&qenc_p, g_qenc);
    cudaGetSymbolAddress((void**)&v_p, g_v);
    cudaGetSymbolAddress((void**)&cntA_p, g_cntA);
    cudaGetSymbolAddress((void**)&cntB_p, g_cntB);

    cudaStream_t s2;
    cudaStreamCreateWithFlags(&s2, cudaStreamNonBlocking);
    cudaEvent_t ef, ec, e3, ej;
    cudaEventCreateWithFlags(&ef, cudaEventDisableTiming);
    cudaEventCreateWithFlags(&ec, cudaEventDisableTiming);
    cudaEventCreateWithFlags(&e3, cudaEventDisableTiming);
    cudaEventCreateWithFlags(&ej, cudaEventDisableTiming);

    // (1)(2) dedup pipeline on s2
    cudaEventRecord(ef, 0);
    cudaStreamWaitEvent(s2, ef, 0);
    k_mark<<<B, 256, 0, s2>>>(docs, plen);
    k_compact<<<(V + 255) / 256, 256, 0, s2>>>();
    cudaEventRecord(ec, s2);

    // (3)(4)(5) encode chain on stream 0 (gemm has fused deterministic reduce)
    k_qrep<<<dim3(B, 8), 256>>>(queries, qlen, emb);
    k_gemm<<<dim3(2048 / TILE_N, KSPLIT), 256>>>(qrep_p, W, 0, qenc_p, bias, 1, cntA_p);
    cudaEventRecord(e3, 0);                        // qenc ready
    k_gemm<<<dim3(2048 / TILE_N, KSPLIT), 256>>>(qenc_p, W, 1, v_p, bias, 0, cntB_p);

    // (6) ydot: needs ids+masks (ec) and v (stream 0 order)  <-- ncu captures this
    cudaStreamWaitEvent(0, ec, 0);
    k_ydot<<<dim3(VPAD / YROWS, KCH), 256>>>(emb);

    // (7) qc off the critical path on s2 (needs qenc)
    cudaStreamWaitEvent(s2, e3, 0);
    k_qc<<<B, 256, 0, s2>>>(bias);
    cudaEventRecord(ej, s2);

    // (8) scatter: needs ydot (stream 0) and qc (ej)
    cudaStreamWaitEvent(0, ej, 0);
    k_scatter<<<B * P, 128>>>(docs, plen, out);
}

// round 13
// speedup vs baseline: 1.1382x; 1.1382x over previous
#include <cuda_runtime.h>
#include <cuda_bf16.h>

// Problem constants
#define B    32
#define LQ   32
#define DLEN 4096
#define P    16
#define D    2048
#define H    2048
#define V    50257
#define VPAD 50432            // 394 * 128

#define KSPLIT 32             // k-split for skinny GEMMs
#define TILE_N 64
#define KB     64
#define YROWS  128            // compact rows per ydot block

// ---------------- scratch (device globals; no allocation allowed) ----------------
__device__ float g_qrep[B * D];
__device__ float g_qenc[B * H];
__device__ float g_v[B * D];
__device__ float g_part[KSPLIT * B * 2048];      // GEMM partials (8 MB)
__device__ float g_c[B];
__device__ unsigned int g_mask[VPAD];            // per-id batch mask; self-cleaned
__device__ int   g_ids[VPAD];
__device__ unsigned int g_cmask[VPAD];
__device__ int   g_rank[V];
__device__ int   g_nids;
__device__ float g_yp[(size_t)VPAD * 256];       // partials [slot][b*8 + z]

// ---------------- mark: batch mask per used vocab id (also zeroes g_nids) ----------
__global__ void k_mark(const int* __restrict__ docs,
                       const int* __restrict__ plen) {
    int b = blockIdx.x;
    __shared__ int tot;
    if (threadIdx.x == 0) {
        int s = 0;
        #pragma unroll
        for (int q = 0; q < P; q++) s += plen[b * P + q];
        tot = s;
        if (b == 0) g_nids = 0;   // no reader until k_compact (next kernel)
    }
    __syncthreads();
    unsigned bit = 1u << b;
    for (int tt = threadIdx.x; tt < tot; tt += blockDim.x)
        atomicOr(&g_mask[docs[b * DLEN + tt]], bit);
}

// ---------------- compact used ids + masks; block-aggregated atomics ---------------
__global__ void k_compact() {
    __shared__ int warp_off[8];
    __shared__ int block_base;
    int i = blockIdx.x * 256 + threadIdx.x;
    unsigned m = (i < V) ? g_mask[i] : 0u;
    bool has = (m != 0u);
    if (has) g_mask[i] = 0u;                     // self-clean for next call
    unsigned ballot = __ballot_sync(0xFFFFFFFFu, has);
    int w = threadIdx.x >> 5, lane = threadIdx.x & 31;
    if (lane == 0) warp_off[w] = __popc(ballot);
    __syncthreads();
    if (threadIdx.x == 0) {
        int tot = 0;
        #pragma unroll
        for (int j = 0; j < 8; j++) { int c = warp_off[j]; warp_off[j] = tot; tot += c; }
        block_base = tot ? atomicAdd(&g_nids, tot) : 0;
    }
    __syncthreads();
    if (has) {
        int slot = block_base + warp_off[w] + __popc(ballot & ((1u << lane) - 1u));
        g_ids[slot] = i;
        g_cmask[slot] = m;
        g_rank[i] = slot;
    }
}

// ---------------- q_rep = masked mean of query token embeddings ----------------
__global__ void k_qrep(const int* __restrict__ queries,
                       const int* __restrict__ qlen,
                       const float* __restrict__ emb) {
    int b = blockIdx.x;
    __shared__ int toks[LQ];
    if (threadIdx.x < LQ) toks[threadIdx.x] = queries[b * LQ + threadIdx.x];
    int len = qlen[b];
    __syncthreads();
    float inv = 1.0f / (float)len;
    int d = blockIdx.y * 256 + threadIdx.x;
    float s = 0.0f;
    for (int l = 0; l < len; l++) s += emb[(size_t)toks[l] * D + d];
    g_qrep[b * D + d] = s * inv;
}

// ---------------- skinny GEMM, vectorized loads: partials to g_part ----------------
__global__ void k_gemm(const float* __restrict__ A,
                       const float* __restrict__ W,
                       int transW) {
    const int n0 = blockIdx.x * TILE_N;
    const int k0 = blockIdx.y * KB;
    __shared__ float As[32][KB];
    __shared__ float Ws[TILE_N][KB + 1];

    const int t  = threadIdx.x;      // 256 threads
    const int tb = t >> 5;
    const int tn = t & 31;

    // A tile: 512 float4, 2 per thread
    #pragma unroll
    for (int i = 0; i < 2; i++) {
        int f4 = t + i * 256;
        int bb = f4 >> 4, k4 = f4 & 15;
        float4 x = *(const float4*)(A + bb * 2048 + k0 + k4 * 4);
        As[bb][k4 * 4 + 0] = x.x; As[bb][k4 * 4 + 1] = x.y;
        As[bb][k4 * 4 + 2] = x.z; As[bb][k4 * 4 + 3] = x.w;
    }
    // W tile: 1024 float4, 4 per thread
    if (!transW) {
        #pragma unroll
        for (int i = 0; i < 4; i++) {
            int f4 = t + i * 256;
            int nn = f4 >> 4, k4 = f4 & 15;
            float4 x = *(const float4*)(W + (size_t)(n0 + nn) * 2048 + k0 + k4 * 4);
            Ws[nn][k4 * 4 + 0] = x.x; Ws[nn][k4 * 4 + 1] = x.y;
            Ws[nn][k4 * 4 + 2] = x.z; Ws[nn][k4 * 4 + 3] = x.w;
        }
    } else {
        #pragma unroll
        for (int i = 0; i < 4; i++) {
            int f4 = t + i * 256;
            int kk = f4 >> 4, n4 = f4 & 15;
            float4 x = *(const float4*)(W + (size_t)(k0 + kk) * 2048 + n0 + n4 * 4);
            Ws[n4 * 4 + 0][kk] = x.x; Ws[n4 * 4 + 1][kk] = x.y;
            Ws[n4 * 4 + 2][kk] = x.z; Ws[n4 * 4 + 3][kk] = x.w;
        }
    }
    __syncthreads();

    float acc00 = 0.f, acc01 = 0.f, acc10 = 0.f, acc11 = 0.f;
    float acc20 = 0.f, acc21 = 0.f, acc30 = 0.f, acc31 = 0.f;
    #pragma unroll 16
    for (int k = 0; k < KB; k++) {
        float a0 = As[tb * 4 + 0][k];
        float a1 = As[tb * 4 + 1][k];
        float a2 = As[tb * 4 + 2][k];
        float a3 = As[tb * 4 + 3][k];
        float w0 = Ws[tn][k];
        float w1 = Ws[tn + 32][k];
        acc00 += a0 * w0; acc01 += a0 * w1;
        acc10 += a1 * w0; acc11 += a1 * w1;
        acc20 += a2 * w0; acc21 += a2 * w1;
        acc30 += a3 * w0; acc31 += a3 * w1;
    }

    float* out = g_part + (size_t)blockIdx.y * 32 * 2048;
    out[(tb * 4 + 0) * 2048 + n0 + tn]      = acc00;
    out[(tb * 4 + 0) * 2048 + n0 + tn + 32] = acc01;
    out[(tb * 4 + 1) * 2048 + n0 + tn]      = acc10;
    out[(tb * 4 + 1) * 2048 + n0 + tn + 32] = acc11;
    out[(tb * 4 + 2) * 2048 + n0 + tn]      = acc20;
    out[(tb * 4 + 2) * 2048 + n0 + tn + 32] = acc21;
    out[(tb * 4 + 3) * 2048 + n0 + tn]      = acc30;
    out[(tb * 4 + 3) * 2048 + n0 + tn + 32] = acc31;
}

// vectorized partial reduce over 16384 float4; 128 blocks x 128 threads
__global__ void k_reduce(float* __restrict__ C,
                         const float* __restrict__ bias,
                         int addBias) {
    int idx = blockIdx.x * 128 + threadIdx.x;
    const float4* part4 = (const float4*)g_part;
    float4 s = make_float4(0.f, 0.f, 0.f, 0.f);
    #pragma unroll
    for (int sp = 0; sp < KSPLIT; sp++) {
        float4 x = part4[sp * 16384 + idx];
        s.x += x.x; s.y += x.y; s.z += x.z; s.w += x.w;
    }
    if (addBias) {
        float4 bb = ((const float4*)bias)[idx & 511];
        s.x += bb.x; s.y += bb.y; s.z += bb.z; s.w += bb.w;
    }
    ((float4*)C)[idx] = s;
}

// c[b] = q_enc[b] . bias
__global__ void k_qc(const float* __restrict__ bias) {
    int b = blockIdx.x;
    float s = 0.0f;
    for (int i = threadIdx.x; i < H; i += 256) s += g_qenc[b * H + i] * bias[i];
    __shared__ float red[256];
    red[threadIdx.x] = s;
    __syncthreads();
    for (int o = 128; o; o >>= 1) {
        if (threadIdx.x < o) red[threadIdx.x] += red[threadIdx.x + o];
        __syncthreads();
    }
    if (threadIdx.x == 0) g_c[b] = red[0];
}

// ---------------- ydot: per compact row, dot against ONLY the batches in its mask ----
// grid (8, VPAD/YROWS): z = blockIdx.x (FAST axis), rowgroup = blockIdx.y.
// Consecutive bids = the 8 z-chunks of the SAME 128 rows -> they land on adjacent
// SMs in the same wave, so each emb row's full 8KB is pulled in one time window
// (DRAM page locality). Block stages its 32 KB v chunk once; one warp per 16 rows;
// sector-perfect lane loads; dual-batch shfl interleave.
__global__ __launch_bounds__(256, 5) void k_ydot(const float* __restrict__ emb) {
    const int z  = blockIdx.x;
    const int m0 = blockIdx.y * YROWS;
    const int nids = g_nids;
    if (m0 >= nids) return;

    __shared__ float4 vs[32][64];    // v chunk [b][j], 32 KB
    __shared__ int ids_s[YROWS];
    __shared__ unsigned mask_s[YROWS];

    const int t = threadIdx.x, w = t >> 5, lane = t & 31;

    #pragma unroll
    for (int i = 0; i < 8; i++) {
        int idx = t + i * 256;               // 0..2047 float4s
        int b = idx >> 6, j = idx & 63;
        vs[b][j] = *(const float4*)(g_v + (size_t)b * D + z * 256 + j * 4);
    }
    if (t < YROWS) {
        int gi = m0 + t;
        bool val = gi < nids;
        ids_s[t]  = val ? g_ids[gi] : 0;
        mask_s[t] = val ? g_cmask[gi] : 0u;
    }
    __syncthreads();

    const int rbase = w * 16;                // warp w handles 16 rows
    const size_t zoffs = (size_t)z * 256;

    // depth-2 row pipeline; lane loads CONTIGUOUS float4s (full-sector LDG.128)
    float4 ba0, bb0, ba1, bb1;
    {
        const float4* rp = (const float4*)(emb + (size_t)ids_s[rbase] * D + zoffs);
        ba0 = rp[lane]; bb0 = rp[lane + 32];
    }
    {
        const float4* rp = (const float4*)(emb + (size_t)ids_s[rbase + 1] * D + zoffs);
        ba1 = rp[lane]; bb1 = rp[lane + 32];
    }

    #pragma unroll 1
    for (int r = 0; r < 16; r++) {
        float4 ea, eb;
        if (r & 1) { ea = ba1; eb = bb1; } else { ea = ba0; eb = bb0; }
        if (r + 2 < 16) {
            const float4* rp = (const float4*)(emb + (size_t)ids_s[rbase + r + 2] * D + zoffs);
            if (r & 1) { ba1 = rp[lane]; bb1 = rp[lane + 32]; }
            else       { ba0 = rp[lane]; bb0 = rp[lane + 32]; }
        }
        unsigned mask = mask_s[rbase + r];
        const int slot = m0 + rbase + r;
        while (mask) {
            int b0 = __ffs(mask) - 1; mask &= mask - 1;
            int b1 = -1;
            if (mask) { b1 = __ffs(mask) - 1; mask &= mask - 1; }
            float4 v0a = vs[b0][lane], v0b = vs[b0][lane + 32];
            float s0 = ea.x * v0a.x + ea.y * v0a.y + ea.z * v0a.z + ea.w * v0a.w
                     + eb.x * v0b.x + eb.y * v0b.y + eb.z * v0b.z + eb.w * v0b.w;
            float s1 = 0.0f;
            if (b1 >= 0) {
                float4 v1a = vs[b1][lane], v1b = vs[b1][lane + 32];
                s1 = ea.x * v1a.x + ea.y * v1a.y + ea.z * v1a.z + ea.w * v1a.w
                   + eb.x * v1b.x + eb.y * v1b.y + eb.z * v1b.z + eb.w * v1b.w;
            }
            // two independent shfl chains, interleaved -> latency overlapped
            #pragma unroll
            for (int o = 16; o; o >>= 1) {
                s0 += __shfl_xor_sync(0xFFFFFFFFu, s0, o);
                s1 += __shfl_xor_sync(0xFFFFFFFFu, s1, o);
            }
            if (lane == 0) {
                g_yp[(size_t)slot * 256 + b0 * 8 + z] = s0;          // [slot][b][z]
                if (b1 >= 0) g_yp[(size_t)slot * 256 + b1 * 8 + z] = s1;
            }
        }
    }
}

// ---------------- scatter: score[b,p] = mean_token sum_z yp[rank[tok]][b][z] + c[b] --
__global__ void k_scatter(const int* __restrict__ docs,
                          const int* __restrict__ plen,
                          float* __restrict__ out) {
    const int bp = blockIdx.x;           // 512 blocks
    const int b = bp >> 4, p = bp & 15;
    const int t = threadIdx.x;           // 128 threads
    __shared__ int info[2];
    __shared__ float red[128];

    if (t == 0) {
        int start = 0;
        for (int q = 0; q < p; q++) start += plen[b * P + q];
        info[0] = start;
        info[1] = plen[b * P + p];
    }
    __syncthreads();
    const int start = info[0], len = info[1];

    float s = 0.0f;
    for (int tt = t; tt < len; tt += 128) {
        int tok = docs[b * DLEN + start + tt];
        const float4* yb = (const float4*)(g_yp + (size_t)g_rank[tok] * 256 + b * 8);
        float4 y0 = yb[0], y1 = yb[1];
        // fixed summation order over the 8 k-chunks -> deterministic
        s += ((y0.x + y0.y) + (y0.z + y0.w)) + ((y1.x + y1.y) + (y1.z + y1.w));
    }
    red[t] = s;
    __syncthreads();
    for (int o = 64; o; o >>= 1) {
        if (t < o) red[t] += red[t + o];
        __syncthreads();
    }
    if (t == 0) {
        float denom = (float)(len > 0 ? len : 1);
        out[bp] = (len > 0) ? (red[0] / denom + g_c[b]) : 0.0f;
    }
}

// ---------------- launch: 2 streams (3-stream graphs leak upload memory) ------------
extern "C" void kernel_launch(void* const* d_in, const int* in_sizes, int n_in,
                              void* d_out, int out_size) {
    const int*   queries = (const int*)d_in[0];
    const int*   qlen    = (const int*)d_in[1];
    const int*   docs    = (const int*)d_in[2];
    const int*   plen    = (const int*)d_in[3];
    const float* emb     = (const float*)d_in[4];
    const float* W       = (const float*)d_in[5];
    const float* bias    = (const float*)d_in[6];
    float*       out     = (float*)d_out;

    float *qrep_p, *qenc_p, *v_p;
    cudaGetSymbolAddress((void**)&qrep_p, g_qrep);
    cudaGetSymbolAddress((void**)&qenc_p, g_qenc);
    cudaGetSymbolAddress((void**)&v_p, g_v);

    cudaStream_t s2;
    cudaStreamCreateWithFlags(&s2, cudaStreamNonBlocking);
    cudaEvent_t ef, ec, e3, ej;
    cudaEventCreateWithFlags(&ef, cudaEventDisableTiming);
    cudaEventCreateWithFlags(&ec, cudaEventDisableTiming);
    cudaEventCreateWithFlags(&e3, cudaEventDisableTiming);
    cudaEventCreateWithFlags(&ej, cudaEventDisableTiming);

    // dedup pipeline on s2
    cudaEventRecord(ef, 0);
    cudaStreamWaitEvent(s2, ef, 0);
    k_mark<<<B, 256, 0, s2>>>(docs, plen);
    k_compact<<<(V + 255) / 256, 256, 0, s2>>>();
    cudaEventRecord(ec, s2);

    // encode chain on stream 0
    k_qrep<<<dim3(B, 8), 256>>>(queries, qlen, emb);
    k_gemm<<<dim3(32, KSPLIT), 256>>>(qrep_p, W, 0);
    k_reduce<<<128, 128>>>(qenc_p, bias, 1);
    cudaEventRecord(e3, 0);                        // qenc ready
    k_gemm<<<dim3(32, KSPLIT), 256>>>(qenc_p, W, 1);
    k_reduce<<<128, 128>>>(v_p, bias, 0);          // v ready

    // ydot: needs ids+masks (ec) and v (stream 0 order); z is the FAST grid axis
    cudaStreamWaitEvent(0, ec, 0);
    k_ydot<<<dim3(8, VPAD / YROWS), 256>>>(emb);

    // qc off the critical path on s2 (needs qenc)
    cudaStreamWaitEvent(s2, e3, 0);
    k_qc<<<B, 256, 0, s2>>>(bias);
    cudaEventRecord(ej, s2);

    // scatter: needs ydot (stream 0) and qc (ej)
    cudaStreamWaitEvent(0, ej, 0);
    k_scatter<<<B * P, 128>>>(docs, plen, out);
}

// round 14
// speedup vs baseline: 1.1579x; 1.0174x over previous
#include <cuda_runtime.h>
#include <cuda_bf16.h>

// Problem constants
#define B    32
#define LQ   32
#define DLEN 4096
#define P    16
#define D    2048
#define H    2048
#define V    50257
#define VPAD 50432            // 394 * 128

#define KSPLIT 32             // k-split for skinny GEMMs
#define TILE_N 64
#define KB     64
#define KCH    4              // k-chunks in ydot (512 d's = 2KB each)
#define YROWS  128            // compact rows per ydot block

// dynamic smem for ydot: v chunk 64KB + ids/masks
#define YD_VS_BYTES (32 * 512 * 4)
#define YD_SMEM     (YD_VS_BYTES + YROWS * 8)

// ---------------- scratch (device globals; no allocation allowed) ----------------
__device__ float g_qrep[B * D];
__device__ float g_qenc[B * H];
__device__ float g_v[B * D];
__device__ float g_part[KSPLIT * B * 2048];      // GEMM partials (8 MB)
__device__ float g_c[B];
__device__ unsigned int g_mask[VPAD];            // per-id batch mask; self-cleaned
__device__ int   g_ids[VPAD];
__device__ unsigned int g_cmask[VPAD];
__device__ int   g_rank[V];
__device__ int   g_nids;
__device__ float g_yp[(size_t)VPAD * 128];       // partials [slot][b*4 + z]

// ---------------- mark: batch mask per used vocab id (also zeroes g_nids) ----------
__global__ void k_mark(const int* __restrict__ docs,
                       const int* __restrict__ plen) {
    int b = blockIdx.x;
    __shared__ int tot;
    if (threadIdx.x == 0) {
        int s = 0;
        #pragma unroll
        for (int q = 0; q < P; q++) s += plen[b * P + q];
        tot = s;
        if (b == 0) g_nids = 0;   // no reader until k_compact (next kernel)
    }
    __syncthreads();
    unsigned bit = 1u << b;
    for (int tt = threadIdx.x; tt < tot; tt += blockDim.x)
        atomicOr(&g_mask[docs[b * DLEN + tt]], bit);
}

// ---------------- compact used ids + masks; block-aggregated atomics ---------------
__global__ void k_compact() {
    __shared__ int warp_off[8];
    __shared__ int block_base;
    int i = blockIdx.x * 256 + threadIdx.x;
    unsigned m = (i < V) ? g_mask[i] : 0u;
    bool has = (m != 0u);
    if (has) g_mask[i] = 0u;                     // self-clean for next call
    unsigned ballot = __ballot_sync(0xFFFFFFFFu, has);
    int w = threadIdx.x >> 5, lane = threadIdx.x & 31;
    if (lane == 0) warp_off[w] = __popc(ballot);
    __syncthreads();
    if (threadIdx.x == 0) {
        int tot = 0;
        #pragma unroll
        for (int j = 0; j < 8; j++) { int c = warp_off[j]; warp_off[j] = tot; tot += c; }
        block_base = tot ? atomicAdd(&g_nids, tot) : 0;
    }
    __syncthreads();
    if (has) {
        int slot = block_base + warp_off[w] + __popc(ballot & ((1u << lane) - 1u));
        g_ids[slot] = i;
        g_cmask[slot] = m;
        g_rank[i] = slot;
    }
}

// ---------------- q_rep = masked mean of query token embeddings ----------------
__global__ void k_qrep(const int* __restrict__ queries,
                       const int* __restrict__ qlen,
                       const float* __restrict__ emb) {
    int b = blockIdx.x;
    __shared__ int toks[LQ];
    if (threadIdx.x < LQ) toks[threadIdx.x] = queries[b * LQ + threadIdx.x];
    int len = qlen[b];
    __syncthreads();
    float inv = 1.0f / (float)len;
    int d = blockIdx.y * 256 + threadIdx.x;
    float s = 0.0f;
    for (int l = 0; l < len; l++) s += emb[(size_t)toks[l] * D + d];
    g_qrep[b * D + d] = s * inv;
}

// ---------------- skinny GEMM, vectorized loads: partials to g_part ----------------
__global__ void k_gemm(const float* __restrict__ A,
                       const float* __restrict__ W,
                       int transW) {
    const int n0 = blockIdx.x * TILE_N;
    const int k0 = blockIdx.y * KB;
    __shared__ float As[32][KB];
    __shared__ float Ws[TILE_N][KB + 1];

    const int t  = threadIdx.x;      // 256 threads
    const int tb = t >> 5;
    const int tn = t & 31;

    // A tile: 512 float4, 2 per thread
    #pragma unroll
    for (int i = 0; i < 2; i++) {
        int f4 = t + i * 256;
        int bb = f4 >> 4, k4 = f4 & 15;
        float4 x = *(const float4*)(A + bb * 2048 + k0 + k4 * 4);
        As[bb][k4 * 4 + 0] = x.x; As[bb][k4 * 4 + 1] = x.y;
        As[bb][k4 * 4 + 2] = x.z; As[bb][k4 * 4 + 3] = x.w;
    }
    // W tile: 1024 float4, 4 per thread
    if (!transW) {
        #pragma unroll
        for (int i = 0; i < 4; i++) {
            int f4 = t + i * 256;
            int nn = f4 >> 4, k4 = f4 & 15;
            float4 x = *(const float4*)(W + (size_t)(n0 + nn) * 2048 + k0 + k4 * 4);
            Ws[nn][k4 * 4 + 0] = x.x; Ws[nn][k4 * 4 + 1] = x.y;
            Ws[nn][k4 * 4 + 2] = x.z; Ws[nn][k4 * 4 + 3] = x.w;
        }
    } else {
        #pragma unroll
        for (int i = 0; i < 4; i++) {
            int f4 = t + i * 256;
            int kk = f4 >> 4, n4 = f4 & 15;
            float4 x = *(const float4*)(W + (size_t)(k0 + kk) * 2048 + n0 + n4 * 4);
            Ws[n4 * 4 + 0][kk] = x.x; Ws[n4 * 4 + 1][kk] = x.y;
            Ws[n4 * 4 + 2][kk] = x.z; Ws[n4 * 4 + 3][kk] = x.w;
        }
    }
    __syncthreads();

    float acc00 = 0.f, acc01 = 0.f, acc10 = 0.f, acc11 = 0.f;
    float acc20 = 0.f, acc21 = 0.f, acc30 = 0.f, acc31 = 0.f;
    #pragma unroll 16
    for (int k = 0; k < KB; k++) {
        float a0 = As[tb * 4 + 0][k];
        float a1 = As[tb * 4 + 1][k];
        float a2 = As[tb * 4 + 2][k];
        float a3 = As[tb * 4 + 3][k];
        float w0 = Ws[tn][k];
        float w1 = Ws[tn + 32][k];
        acc00 += a0 * w0; acc01 += a0 * w1;
        acc10 += a1 * w0; acc11 += a1 * w1;
        acc20 += a2 * w0; acc21 += a2 * w1;
        acc30 += a3 * w0; acc31 += a3 * w1;
    }

    float* out = g_part + (size_t)blockIdx.y * 32 * 2048;
    out[(tb * 4 + 0) * 2048 + n0 + tn]      = acc00;
    out[(tb * 4 + 0) * 2048 + n0 + tn + 32] = acc01;
    out[(tb * 4 + 1) * 2048 + n0 + tn]      = acc10;
    out[(tb * 4 + 1) * 2048 + n0 + tn + 32] = acc11;
    out[(tb * 4 + 2) * 2048 + n0 + tn]      = acc20;
    out[(tb * 4 + 2) * 2048 + n0 + tn + 32] = acc21;
    out[(tb * 4 + 3) * 2048 + n0 + tn]      = acc30;
    out[(tb * 4 + 3) * 2048 + n0 + tn + 32] = acc31;
}

// vectorized partial reduce over 16384 float4; 128 blocks x 128 threads
__global__ void k_reduce(float* __restrict__ C,
                         const float* __restrict__ bias,
                         int addBias) {
    int idx = blockIdx.x * 128 + threadIdx.x;
    const float4* part4 = (const float4*)g_part;
    float4 s = make_float4(0.f, 0.f, 0.f, 0.f);
    #pragma unroll
    for (int sp = 0; sp < KSPLIT; sp++) {
        float4 x = part4[sp * 16384 + idx];
        s.x += x.x; s.y += x.y; s.z += x.z; s.w += x.w;
    }
    if (addBias) {
        float4 bb = ((const float4*)bias)[idx & 511];
        s.x += bb.x; s.y += bb.y; s.z += bb.z; s.w += bb.w;
    }
    ((float4*)C)[idx] = s;
}

// c[b] = q_enc[b] . bias
__global__ void k_qc(const float* __restrict__ bias) {
    int b = blockIdx.x;
    float s = 0.0f;
    for (int i = threadIdx.x; i < H; i += 256) s += g_qenc[b * H + i] * bias[i];
    __shared__ float red[256];
    red[threadIdx.x] = s;
    __syncthreads();
    for (int o = 128; o; o >>= 1) {
        if (threadIdx.x < o) red[threadIdx.x] += red[threadIdx.x + o];
        __syncthreads();
    }
    if (threadIdx.x == 0) g_c[b] = red[0];
}

// ---------------- ydot: per compact row, dot against ONLY the batches in its mask ----
// grid (KCH=4, VPAD/YROWS): z fast axis -> the 4 z-chunks of the same 128 rows are
// co-resident. Each block covers a 2KB slice of each row (4 contiguous LDG.128/lane)
// -> half the DRAM fragmentation of the 1KB version. v chunk (64KB) in dynamic smem.
__global__ __launch_bounds__(256, 3) void k_ydot(const float* __restrict__ emb) {
    extern __shared__ char sm_raw[];
    float4*   vs     = (float4*)sm_raw;                       // [b*128 + j], 64KB
    int*      ids_s  = (int*)(sm_raw + YD_VS_BYTES);
    unsigned* mask_s = (unsigned*)(ids_s + YROWS);

    const int z  = blockIdx.x;          // 0..3
    const int m0 = blockIdx.y * YROWS;
    const int nids = g_nids;
    if (m0 >= nids) return;

    const int t = threadIdx.x, w = t >> 5, lane = t & 31;

    // stage v chunk: 4096 float4s, 16 per thread
    #pragma unroll
    for (int i = 0; i < 16; i++) {
        int idx = t + i * 256;
        int b = idx >> 7, j = idx & 127;
        vs[b * 128 + j] = *(const float4*)(g_v + (size_t)b * D + z * 512 + j * 4);
    }
    if (t < YROWS) {
        int gi = m0 + t;
        bool val = gi < nids;
        ids_s[t]  = val ? g_ids[gi] : 0;
        mask_s[t] = val ? g_cmask[gi] : 0u;
    }
    __syncthreads();

    const int rbase = w * 16;                // warp w handles 16 rows
    const size_t zoffs = (size_t)z * 512;

    // depth-2 row pipeline; per row 4 contiguous LDG.128/lane (2KB slice)
    float4 c0a, c0b, c0c, c0d, c1a, c1b, c1c, c1d;
    {
        const float4* rp = (const float4*)(emb + (size_t)ids_s[rbase] * D + zoffs);
        c0a = rp[lane]; c0b = rp[lane + 32]; c0c = rp[lane + 64]; c0d = rp[lane + 96];
    }
    {
        const float4* rp = (const float4*)(emb + (size_t)ids_s[rbase + 1] * D + zoffs);
        c1a = rp[lane]; c1b = rp[lane + 32]; c1c = rp[lane + 64]; c1d = rp[lane + 96];
    }

    #pragma unroll 1
    for (int r = 0; r < 16; r++) {
        float4 ea, eb, ec, ed;
        if (r & 1) { ea = c1a; eb = c1b; ec = c1c; ed = c1d; }
        else       { ea = c0a; eb = c0b; ec = c0c; ed = c0d; }
        if (r + 2 < 16) {
            const float4* rp = (const float4*)(emb + (size_t)ids_s[rbase + r + 2] * D + zoffs);
            if (r & 1) { c1a = rp[lane]; c1b = rp[lane + 32]; c1c = rp[lane + 64]; c1d = rp[lane + 96]; }
            else       { c0a = rp[lane]; c0b = rp[lane + 32]; c0c = rp[lane + 64]; c0d = rp[lane + 96]; }
        }
        unsigned mask = mask_s[rbase + r];
        const int slot = m0 + rbase + r;
        while (mask) {
            int b0 = __ffs(mask) - 1; mask &= mask - 1;
            int b1 = -1;
            if (mask) { b1 = __ffs(mask) - 1; mask &= mask - 1; }
            const float4* vp0 = &vs[b0 * 128];
            float4 va = vp0[lane], vb = vp0[lane + 32], vc = vp0[lane + 64], vd = vp0[lane + 96];
            float s0 = ea.x * va.x + ea.y * va.y + ea.z * va.z + ea.w * va.w
                     + eb.x * vb.x + eb.y * vb.y + eb.z * vb.z + eb.w * vb.w
                     + ec.x * vc.x + ec.y * vc.y + ec.z * vc.z + ec.w * vc.w
                     + ed.x * vd.x + ed.y * vd.y + ed.z * vd.z + ed.w * vd.w;
            float s1 = 0.0f;
            if (b1 >= 0) {
                const float4* vp1 = &vs[b1 * 128];
                float4 wa = vp1[lane], wb = vp1[lane + 32], wc = vp1[lane + 64], wd = vp1[lane + 96];
                s1 = ea.x * wa.x + ea.y * wa.y + ea.z * wa.z + ea.w * wa.w
                   + eb.x * wb.x + eb.y * wb.y + eb.z * wb.z + eb.w * wb.w
                   + ec.x * wc.x + ec.y * wc.y + ec.z * wc.z + ec.w * wc.w
                   + ed.x * wd.x + ed.y * wd.y + ed.z * wd.z + ed.w * wd.w;
            }
            // two independent shfl chains, interleaved -> latency overlapped
            #pragma unroll
            for (int o = 16; o; o >>= 1) {
                s0 += __shfl_xor_sync(0xFFFFFFFFu, s0, o);
                s1 += __shfl_xor_sync(0xFFFFFFFFu, s1, o);
            }
            if (lane == 0) {
                g_yp[(size_t)slot * 128 + b0 * 4 + z] = s0;          // [slot][b][z]
                if (b1 >= 0) g_yp[(size_t)slot * 128 + b1 * 4 + z] = s1;
            }
        }
    }
}

// ---------------- scatter: score[b,p] = mean_token sum_z yp[rank[tok]][b][z] + c[b] --
__global__ void k_scatter(const int* __restrict__ docs,
                          const int* __restrict__ plen,
                          float* __restrict__ out) {
    const int bp = blockIdx.x;           // 512 blocks
    const int b = bp >> 4, p = bp & 15;
    const int t = threadIdx.x;           // 128 threads
    __shared__ int info[2];
    __shared__ float red[128];

    if (t == 0) {
        int start = 0;
        for (int q = 0; q < p; q++) start += plen[b * P + q];
        info[0] = start;
        info[1] = plen[b * P + p];
    }
    __syncthreads();
    const int start = info[0], len = info[1];

    float s = 0.0f;
    for (int tt = t; tt < len; tt += 128) {
        int tok = docs[b * DLEN + start + tt];
        float4 y = *(const float4*)(g_yp + (size_t)g_rank[tok] * 128 + b * 4);
        // fixed summation order over the 4 k-chunks -> deterministic
        s += (y.x + y.y) + (y.z + y.w);
    }
    red[t] = s;
    __syncthreads();
    for (int o = 64; o; o >>= 1) {
        if (t < o) red[t] += red[t + o];
        __syncthreads();
    }
    if (t == 0) {
        float denom = (float)(len > 0 ? len : 1);
        out[bp] = (len > 0) ? (red[0] / denom + g_c[b]) : 0.0f;
    }
}

// ---------------- launch: 2 streams (3-stream graphs leak upload memory) ------------
extern "C" void kernel_launch(void* const* d_in, const int* in_sizes, int n_in,
                              void* d_out, int out_size) {
    const int*   queries = (const int*)d_in[0];
    const int*   qlen    = (const int*)d_in[1];
    const int*   docs    = (const int*)d_in[2];
    const int*   plen    = (const int*)d_in[3];
    const float* emb     = (const float*)d_in[4];
    const float* W       = (const float*)d_in[5];
    const float* bias    = (const float*)d_in[6];
    float*       out     = (float*)d_out;

    float *qrep_p, *qenc_p, *v_p;
    cudaGetSymbolAddress((void**)&qrep_p, g_qrep);
    cudaGetSymbolAddress((void**)&qenc_p, g_qenc);
    cudaGetSymbolAddress((void**)&v_p, g_v);

    cudaFuncSetAttribute(k_ydot, cudaFuncAttributeMaxDynamicSharedMemorySize, YD_SMEM);

    cudaStream_t s2;
    cudaStreamCreateWithFlags(&s2, cudaStreamNonBlocking);
    cudaEvent_t ef, ec, e3, ej;
    cudaEventCreateWithFlags(&ef, cudaEventDisableTiming);
    cudaEventCreateWithFlags(&ec, cudaEventDisableTiming);
    cudaEventCreateWithFlags(&e3, cudaEventDisableTiming);
    cudaEventCreateWithFlags(&ej, cudaEventDisableTiming);

    // dedup pipeline on s2
    cudaEventRecord(ef, 0);
    cudaStreamWaitEvent(s2, ef, 0);
    k_mark<<<B, 256, 0, s2>>>(docs, plen);
    k_compact<<<(V + 255) / 256, 256, 0, s2>>>();
    cudaEventRecord(ec, s2);

    // encode chain on stream 0
    k_qrep<<<dim3(B, 8), 256>>>(queries, qlen, emb);
    k_gemm<<<dim3(32, KSPLIT), 256>>>(qrep_p, W, 0);
    k_reduce<<<128, 128>>>(qenc_p, bias, 1);
    cudaEventRecord(e3, 0);                        // qenc ready
    k_gemm<<<dim3(32, KSPLIT), 256>>>(qenc_p, W, 1);
    k_reduce<<<128, 128>>>(v_p, bias, 0);          // v ready

    // ydot: needs ids+masks (ec) and v (stream 0 order); z is the FAST grid axis
    cudaStreamWaitEvent(0, ec, 0);
    k_ydot<<<dim3(KCH, VPAD / YROWS), 256, YD_SMEM>>>(emb);

    // qc off the critical path on s2 (needs qenc)
    cudaStreamWaitEvent(s2, e3, 0);
    k_qc<<<B, 256, 0, s2>>>(bias);
    cudaEventRecord(ej, s2);

    // scatter: needs ydot (stream 0) and qc (ej)
    cudaStreamWaitEvent(0, ej, 0);
    k_scatter<<<B * P, 128>>>(docs, plen, out);
}

// round 15
// speedup vs baseline: 1.1929x; 1.0302x over previous
#include <cuda_runtime.h>
#include <cuda_bf16.h>

// Problem constants
#define B    32
#define LQ   32
#define DLEN 4096
#define P    16
#define D    2048
#define H    2048
#define V    50257
#define VPAD 50432            // 394 * 128

#define KSPLIT 32             // k-split for skinny GEMMs
#define TILE_N 64
#define KB     64

// ---------------- scratch (device globals; no allocation allowed) ----------------
__device__ float g_qrep[B * D];
__device__ float g_qenc[B * H];
__device__ float g_v[B * D];
__device__ float g_part[KSPLIT * B * 2048];      // GEMM partials (8 MB)
__device__ float g_c[B];
__device__ unsigned int g_mask[VPAD];            // per-id batch mask; self-cleaned
__device__ int   g_ids[VPAD];
__device__ unsigned int g_cmask[VPAD];
__device__ int   g_rank[V];
__device__ int   g_nids;
__device__ float g_y[(size_t)VPAD * B];          // dot table [slot][b] (6.5 MB)

// ---------------- mark: batch mask per used vocab id (also zeroes g_nids) ----------
__global__ void k_mark(const int* __restrict__ docs,
                       const int* __restrict__ plen) {
    int b = blockIdx.x;
    __shared__ int tot;
    if (threadIdx.x == 0) {
        int s = 0;
        #pragma unroll
        for (int q = 0; q < P; q++) s += plen[b * P + q];
        tot = s;
        if (b == 0) g_nids = 0;   // no reader until k_compact (next kernel)
    }
    __syncthreads();
    unsigned bit = 1u << b;
    for (int tt = threadIdx.x; tt < tot; tt += blockDim.x)
        atomicOr(&g_mask[docs[b * DLEN + tt]], bit);
}

// ---------------- compact used ids + masks; block-aggregated atomics ---------------
__global__ void k_compact() {
    __shared__ int warp_off[8];
    __shared__ int block_base;
    int i = blockIdx.x * 256 + threadIdx.x;
    unsigned m = (i < V) ? g_mask[i] : 0u;
    bool has = (m != 0u);
    if (has) g_mask[i] = 0u;                     // self-clean for next call
    unsigned ballot = __ballot_sync(0xFFFFFFFFu, has);
    int w = threadIdx.x >> 5, lane = threadIdx.x & 31;
    if (lane == 0) warp_off[w] = __popc(ballot);
    __syncthreads();
    if (threadIdx.x == 0) {
        int tot = 0;
        #pragma unroll
        for (int j = 0; j < 8; j++) { int c = warp_off[j]; warp_off[j] = tot; tot += c; }
        block_base = tot ? atomicAdd(&g_nids, tot) : 0;
    }
    __syncthreads();
    if (has) {
        int slot = block_base + warp_off[w] + __popc(ballot & ((1u << lane) - 1u));
        g_ids[slot] = i;
        g_cmask[slot] = m;
        g_rank[i] = slot;
    }
}

// ---------------- q_rep = masked mean of query token embeddings ----------------
__global__ void k_qrep(const int* __restrict__ queries,
                       const int* __restrict__ qlen,
                       const float* __restrict__ emb) {
    int b = blockIdx.x;
    __shared__ int toks[LQ];
    if (threadIdx.x < LQ) toks[threadIdx.x] = queries[b * LQ + threadIdx.x];
    int len = qlen[b];
    __syncthreads();
    float inv = 1.0f / (float)len;
    int d = blockIdx.y * 256 + threadIdx.x;
    float s = 0.0f;
    for (int l = 0; l < len; l++) s += emb[(size_t)toks[l] * D + d];
    g_qrep[b * D + d] = s * inv;
}

// ---------------- skinny GEMM, vectorized loads: partials to g_part ----------------
__global__ void k_gemm(const float* __restrict__ A,
                       const float* __restrict__ W,
                       int transW) {
    const int n0 = blockIdx.x * TILE_N;
    const int k0 = blockIdx.y * KB;
    __shared__ float As[32][KB];
    __shared__ float Ws[TILE_N][KB + 1];

    const int t  = threadIdx.x;      // 256 threads
    const int tb = t >> 5;
    const int tn = t & 31;

    // A tile: 512 float4, 2 per thread
    #pragma unroll
    for (int i = 0; i < 2; i++) {
        int f4 = t + i * 256;
        int bb = f4 >> 4, k4 = f4 & 15;
        float4 x = *(const float4*)(A + bb * 2048 + k0 + k4 * 4);
        As[bb][k4 * 4 + 0] = x.x; As[bb][k4 * 4 + 1] = x.y;
        As[bb][k4 * 4 + 2] = x.z; As[bb][k4 * 4 + 3] = x.w;
    }
    // W tile: 1024 float4, 4 per thread
    if (!transW) {
        #pragma unroll
        for (int i = 0; i < 4; i++) {
            int f4 = t + i * 256;
            int nn = f4 >> 4, k4 = f4 & 15;
            float4 x = *(const float4*)(W + (size_t)(n0 + nn) * 2048 + k0 + k4 * 4);
            Ws[nn][k4 * 4 + 0] = x.x; Ws[nn][k4 * 4 + 1] = x.y;
            Ws[nn][k4 * 4 + 2] = x.z; Ws[nn][k4 * 4 + 3] = x.w;
        }
    } else {
        #pragma unroll
        for (int i = 0; i < 4; i++) {
            int f4 = t + i * 256;
            int kk = f4 >> 4, n4 = f4 & 15;
            float4 x = *(const float4*)(W + (size_t)(k0 + kk) * 2048 + n0 + n4 * 4);
            Ws[n4 * 4 + 0][kk] = x.x; Ws[n4 * 4 + 1][kk] = x.y;
            Ws[n4 * 4 + 2][kk] = x.z; Ws[n4 * 4 + 3][kk] = x.w;
        }
    }
    __syncthreads();

    float acc00 = 0.f, acc01 = 0.f, acc10 = 0.f, acc11 = 0.f;
    float acc20 = 0.f, acc21 = 0.f, acc30 = 0.f, acc31 = 0.f;
    #pragma unroll 16
    for (int k = 0; k < KB; k++) {
        float a0 = As[tb * 4 + 0][k];
        float a1 = As[tb * 4 + 1][k];
        float a2 = As[tb * 4 + 2][k];
        float a3 = As[tb * 4 + 3][k];
        float w0 = Ws[tn][k];
        float w1 = Ws[tn + 32][k];
        acc00 += a0 * w0; acc01 += a0 * w1;
        acc10 += a1 * w0; acc11 += a1 * w1;
        acc20 += a2 * w0; acc21 += a2 * w1;
        acc30 += a3 * w0; acc31 += a3 * w1;
    }

    float* out = g_part + (size_t)blockIdx.y * 32 * 2048;
    out[(tb * 4 + 0) * 2048 + n0 + tn]      = acc00;
    out[(tb * 4 + 0) * 2048 + n0 + tn + 32] = acc01;
    out[(tb * 4 + 1) * 2048 + n0 + tn]      = acc10;
    out[(tb * 4 + 1) * 2048 + n0 + tn + 32] = acc11;
    out[(tb * 4 + 2) * 2048 + n0 + tn]      = acc20;
    out[(tb * 4 + 2) * 2048 + n0 + tn + 32] = acc21;
    out[(tb * 4 + 3) * 2048 + n0 + tn]      = acc30;
    out[(tb * 4 + 3) * 2048 + n0 + tn + 32] = acc31;
}

// vectorized partial reduce over 16384 float4; 128 blocks x 128 threads
__global__ void k_reduce(float* __restrict__ C,
                         const float* __restrict__ bias,
                         int addBias) {
    int idx = blockIdx.x * 128 + threadIdx.x;
    const float4* part4 = (const float4*)g_part;
    float4 s = make_float4(0.f, 0.f, 0.f, 0.f);
    #pragma unroll
    for (int sp = 0; sp < KSPLIT; sp++) {
        float4 x = part4[sp * 16384 + idx];
        s.x += x.x; s.y += x.y; s.z += x.z; s.w += x.w;
    }
    if (addBias) {
        float4 bb = ((const float4*)bias)[idx & 511];
        s.x += bb.x; s.y += bb.y; s.z += bb.z; s.w += bb.w;
    }
    ((float4*)C)[idx] = s;
}

// c[b] = q_enc[b] . bias
__global__ void k_qc(const float* __restrict__ bias) {
    int b = blockIdx.x;
    float s = 0.0f;
    for (int i = threadIdx.x; i < H; i += 256) s += g_qenc[b * H + i] * bias[i];
    __shared__ float red[256];
    red[threadIdx.x] = s;
    __syncthreads();
    for (int o = 128; o; o >>= 1) {
        if (threadIdx.x < o) red[threadIdx.x] += red[threadIdx.x + o];
        __syncthreads();
    }
    if (threadIdx.x == 0) g_c[b] = red[0];
}

// ---------------- ydot: ONE WARP OWNS ONE FULL ROW --------------------------------
// Warp loads its entire 8KB emb row into registers (16 contiguous LDG.128/lane =
// one 64-line DRAM burst), then dots against each masked batch's v streamed from
// global (v = 256KB, L2/L1-resident). No smem staging, no z-chunking, no partials.
// Consecutive slots hold near-ascending vocab ids -> a block's 8 rows share pages.
__global__ __launch_bounds__(256) void k_ydot(const float* __restrict__ emb) {
    const int t = threadIdx.x, w = t >> 5, lane = t & 31;
    const int row = blockIdx.x * 8 + w;
    if (row >= g_nids) return;

    const int id = g_ids[row];               // uniform per warp (broadcast load)
    unsigned mask = g_cmask[row];
    const float4* rp = (const float4*)(emb + (size_t)id * D);

    // full row into registers: 16 x LDG.128, contiguous 8KB
    float4 e[16];
    #pragma unroll
    for (int i = 0; i < 16; i++) e[i] = rp[lane + 32 * i];

    while (mask) {
        int b0 = __ffs(mask) - 1; mask &= mask - 1;
        int b1 = -1;
        if (mask) { b1 = __ffs(mask) - 1; mask &= mask - 1; }
        const float4* vp0 = (const float4*)(g_v + (size_t)b0 * D);
        const float4* vp1 = (b1 >= 0) ? (const float4*)(g_v + (size_t)b1 * D) : vp0;
        float s0 = 0.0f, s1 = 0.0f;
        #pragma unroll
        for (int i = 0; i < 16; i++) {
            float4 v0 = vp0[lane + 32 * i];
            float4 v1 = vp1[lane + 32 * i];
            s0 += e[i].x * v0.x + e[i].y * v0.y + e[i].z * v0.z + e[i].w * v0.w;
            s1 += e[i].x * v1.x + e[i].y * v1.y + e[i].z * v1.z + e[i].w * v1.w;
        }
        // two independent shfl chains, interleaved -> latency overlapped
        #pragma unroll
        for (int o = 16; o; o >>= 1) {
            s0 += __shfl_xor_sync(0xFFFFFFFFu, s0, o);
            s1 += __shfl_xor_sync(0xFFFFFFFFu, s1, o);
        }
        if (lane == 0) {
            g_y[(size_t)row * B + b0] = s0;
            if (b1 >= 0) g_y[(size_t)row * B + b1] = s1;
        }
    }
}

// ---------------- scatter: score[b,p] = mean_token y[rank[tok]][b] + c[b] ----------
__global__ void k_scatter(const int* __restrict__ docs,
                          const int* __restrict__ plen,
                          float* __restrict__ out) {
    const int bp = blockIdx.x;           // 512 blocks
    const int b = bp >> 4, p = bp & 15;
    const int t = threadIdx.x;           // 128 threads
    __shared__ int info[2];
    __shared__ float red[128];

    if (t == 0) {
        int start = 0;
        for (int q = 0; q < p; q++) start += plen[b * P + q];
        info[0] = start;
        info[1] = plen[b * P + p];
    }
    __syncthreads();
    const int start = info[0], len = info[1];

    float s = 0.0f;
    for (int tt = t; tt < len; tt += 128) {
        int tok = docs[b * DLEN + start + tt];
        s += g_y[(size_t)g_rank[tok] * B + b];
    }
    red[t] = s;
    __syncthreads();
    for (int o = 64; o; o >>= 1) {
        if (t < o) red[t] += red[t + o];
        __syncthreads();
    }
    if (t == 0) {
        float denom = (float)(len > 0 ? len : 1);
        out[bp] = (len > 0) ? (red[0] / denom + g_c[b]) : 0.0f;
    }
}

// ---------------- launch: 2 streams (3-stream graphs leak upload memory) ------------
extern "C" void kernel_launch(void* const* d_in, const int* in_sizes, int n_in,
                              void* d_out, int out_size) {
    const int*   queries = (const int*)d_in[0];
    const int*   qlen    = (const int*)d_in[1];
    const int*   docs    = (const int*)d_in[2];
    const int*   plen    = (const int*)d_in[3];
    const float* emb     = (const float*)d_in[4];
    const float* W       = (const float*)d_in[5];
    const float* bias    = (const float*)d_in[6];
    float*       out     = (float*)d_out;

    float *qrep_p, *qenc_p, *v_p;
    cudaGetSymbolAddress((void**)&qrep_p, g_qrep);
    cudaGetSymbolAddress((void**)&qenc_p, g_qenc);
    cudaGetSymbolAddress((void**)&v_p, g_v);

    cudaStream_t s2;
    cudaStreamCreateWithFlags(&s2, cudaStreamNonBlocking);
    cudaEvent_t ef, ec, e3, ej;
    cudaEventCreateWithFlags(&ef, cudaEventDisableTiming);
    cudaEventCreateWithFlags(&ec, cudaEventDisableTiming);
    cudaEventCreateWithFlags(&e3, cudaEventDisableTiming);
    cudaEventCreateWithFlags(&ej, cudaEventDisableTiming);

    // dedup pipeline on s2
    cudaEventRecord(ef, 0);
    cudaStreamWaitEvent(s2, ef, 0);
    k_mark<<<B, 256, 0, s2>>>(docs, plen);
    k_compact<<<(V + 255) / 256, 256, 0, s2>>>();
    cudaEventRecord(ec, s2);

    // encode chain on stream 0
    k_qrep<<<dim3(B, 8), 256>>>(queries, qlen, emb);
    k_gemm<<<dim3(32, KSPLIT), 256>>>(qrep_p, W, 0);
    k_reduce<<<128, 128>>>(qenc_p, bias, 1);
    cudaEventRecord(e3, 0);                        // qenc ready
    k_gemm<<<dim3(32, KSPLIT), 256>>>(qenc_p, W, 1);
    k_reduce<<<128, 128>>>(v_p, bias, 0);          // v ready

    // ydot: needs ids+masks (ec) and v (stream 0 order); one warp per full row
    cudaStreamWaitEvent(0, ec, 0);
    k_ydot<<<VPAD / 8, 256>>>(emb);

    // qc off the critical path on s2 (needs qenc)
    cudaStreamWaitEvent(s2, e3, 0);
    k_qc<<<B, 256, 0, s2>>>(bias);
    cudaEventRecord(ej, s2);

    // scatter: needs ydot (stream 0) and qc (ej)
    cudaStreamWaitEvent(0, ej, 0);
    k_scatter<<<B * P, 128>>>(docs, plen, out);
}